// round 1
// baseline (speedup 1.0000x reference)
#include <cuda_runtime.h>
#include <math.h>

#define BB 16
#define GG 1600
#define DD 2048
#define MM 64
#define WG 40
#define HG 40
#define CELLS_PER_THR 7   // ceil(1600/256)

// ---- device-global scratch (no allocations allowed) ----
__device__ float g_var[BB * GG];
__device__ float g_loss_sum;
__device__ int   g_pos;

__global__ void init_kernel() {
    g_loss_sum = 0.0f;
    g_pos = 0;
}

// One CTA per (b,g) row: variance over D=2048 with ddof=1.
// Shift by 0.5 before accumulating: values are U[0,1], so this removes the
// catastrophic cancellation in sumsq - sum^2/n (conditioning ~2000x better).
__global__ void __launch_bounds__(256) var_kernel(const float* __restrict__ atten) {
    const int row = blockIdx.x;
    const float4* p = reinterpret_cast<const float4*>(atten + (size_t)row * DD);
    const int t = threadIdx.x;

    float s = 0.0f, s2 = 0.0f;
#pragma unroll
    for (int k = 0; k < 2; k++) {
        float4 v = p[t + k * 256];
        float a0 = v.x - 0.5f, a1 = v.y - 0.5f, a2 = v.z - 0.5f, a3 = v.w - 0.5f;
        s += a0; s += a1; s += a2; s += a3;
        s2 = fmaf(a0, a0, s2);
        s2 = fmaf(a1, a1, s2);
        s2 = fmaf(a2, a2, s2);
        s2 = fmaf(a3, a3, s2);
    }
#pragma unroll
    for (int o = 16; o > 0; o >>= 1) {
        s  += __shfl_xor_sync(0xFFFFFFFFu, s,  o);
        s2 += __shfl_xor_sync(0xFFFFFFFFu, s2, o);
    }
    __shared__ float sh[8], sh2[8];
    if ((t & 31) == 0) { sh[t >> 5] = s; sh2[t >> 5] = s2; }
    __syncthreads();
    if (t == 0) {
        float S = 0.0f, S2 = 0.0f;
#pragma unroll
        for (int i = 0; i < 8; i++) { S += sh[i]; S2 += sh2[i]; }
        g_var[row] = (S2 - S * S / (float)DD) / (float)(DD - 1);
    }
}

// One CTA per batch: compute effective-box corners, run the sequential
// 64-box assignment scan, then reduce per-box variance means into globals.
__global__ void __launch_bounds__(256) assign_kernel(const float* __restrict__ bboxes) {
    const int b = blockIdx.x;
    const int t = threadIdx.x;

    __shared__ float s_cx[MM], s_cy[MM];
    __shared__ float s_corx[MM][4], s_cory[MM][4];
    __shared__ float s_rd[256];
    __shared__ int   s_ri[256];
    __shared__ int   s_free;
    __shared__ float s_sums[MM];
    __shared__ int   s_counts[MM];
    __shared__ float s_loss;
    __shared__ int   s_pos;

    // --- corners for all 64 boxes (threads 0..63) ---
    if (t < MM) {
        const float* bb = bboxes + ((size_t)b * MM + t) * 7;
        float cx = bb[0], cy = bb[1];
        float l = bb[3], w = bb[4];
        float ang = bb[6];
        // ratio = clip(DIM/W / l, 1, 6); eff = l * ratio   (DIM/W = 102.4/40 = 2.56)
        float rl = fminf(fmaxf(2.56f / l, 1.0f), 6.0f);
        float rw = fminf(fmaxf(2.56f / w, 1.0f), 6.0f);
        float el = l * rl, ew = w * rw;
        float c = cosf(ang), sn = sinf(ang);
        const float cnx[4] = {-0.5f, -0.5f, 0.5f, 0.5f};
        const float cny[4] = {-0.5f,  0.5f, 0.5f, -0.5f};
#pragma unroll
        for (int k = 0; k < 4; k++) {
            float lx = cnx[k] * el, ly = cny[k] * ew;
            s_corx[t][k] = c * lx - sn * ly + cx;
            s_cory[t][k] = sn * lx + c * ly + cy;
        }
        s_cx[t] = cx; s_cy[t] = cy;
        s_sums[t] = 0.0f; s_counts[t] = 0;
    }
    if (t == 0) { s_loss = 0.0f; s_pos = 0; }
    __syncthreads();

    // --- per-thread cell ownership (fixed 7 slots so everything stays in regs) ---
    float px[CELLS_PER_THR], py[CELLS_PER_THR];
    int   gidx[CELLS_PER_THR];
    int   flag[CELLS_PER_THR];
    bool  msk[CELLS_PER_THR];
#pragma unroll
    for (int k = 0; k < CELLS_PER_THR; k++) {
        int g = t + k * 256;
        if (g < GG) {
            int wi = g % WG, hi = g / WG;
            px[k] = ((float)wi + 0.5f) / 40.0f * 102.4f - 51.2f;
            py[k] = ((float)hi + 0.5f) / 40.0f * 102.4f - 51.2f;
            gidx[k] = g;
        } else {
            px[k] = 1.0e30f; py[k] = 1.0e30f;
            gidx[k] = -1;
        }
        flag[k] = -1;
    }

    // --- sequential scan over boxes ---
    for (int i = 0; i < MM; i++) {
        const float cx = s_cx[i], cy = s_cy[i];

        // local argmin of squared distance (first-min tie-break via index order)
        float bd = 3.0e38f;
        int   bi = GG + 1;
#pragma unroll
        for (int k = 0; k < CELLS_PER_THR; k++) {
            if (gidx[k] >= 0) {
                float dx = px[k] - cx, dy = py[k] - cy;
                float d = dx * dx + dy * dy;
                // within a thread, gidx increases with k; strict < keeps first min
                if (d < bd) { bd = d; bi = gidx[k]; }
            }
        }
        s_rd[t] = bd; s_ri[t] = bi;
        __syncthreads();
#pragma unroll
        for (int off = 128; off > 0; off >>= 1) {
            if (t < off) {
                float od = s_rd[t + off];
                int   oi = s_ri[t + off];
                if (od < s_rd[t] || (od == s_rd[t] && oi < s_ri[t])) {
                    s_rd[t] = od; s_ri[t] = oi;
                }
            }
            __syncthreads();
        }
        const int gmin = s_ri[0];
        if (t == 0) s_free = 1;
        __syncthreads();

        // inside-test + mask, and local "all masked cells are free" check
        const float x0 = s_corx[i][0], y0 = s_cory[i][0];
        const float x1 = s_corx[i][1], y1 = s_cory[i][1];
        const float x2 = s_corx[i][2], y2 = s_cory[i][2];
        const float x3 = s_corx[i][3], y3 = s_cory[i][3];
        const float e0x = x1 - x0, e0y = y1 - y0;
        const float e1x = x2 - x1, e1y = y2 - y1;
        const float e2x = x3 - x2, e2y = y3 - y2;
        const float e3x = x0 - x3, e3y = y0 - y3;

        bool localfree = true;
#pragma unroll
        for (int k = 0; k < CELLS_PER_THR; k++) {
            bool m = false;
            if (gidx[k] >= 0) {
                float c0 = e0x * (py[k] - y0) - e0y * (px[k] - x0);
                float c1 = e1x * (py[k] - y1) - e1y * (px[k] - x1);
                float c2 = e2x * (py[k] - y2) - e2y * (px[k] - x2);
                float c3 = e3x * (py[k] - y3) - e3y * (px[k] - x3);
                bool allpos = (c0 >= 0.0f) & (c1 >= 0.0f) & (c2 >= 0.0f) & (c3 >= 0.0f);
                bool allneg = (c0 <= 0.0f) & (c1 <= 0.0f) & (c2 <= 0.0f) & (c3 <= 0.0f);
                m = allpos | allneg | (gidx[k] == gmin);
                if (m && flag[k] != -1) localfree = false;
            }
            msk[k] = m;
        }
        if (!localfree) s_free = 0;   // all writers write 0: race-free
        __syncthreads();
        const bool all_free = (s_free != 0);
#pragma unroll
        for (int k = 0; k < CELLS_PER_THR; k++) {
            if (msk[k]) flag[k] = (all_free || flag[k] == -1) ? i : -1;
        }
        __syncthreads();   // protect s_rd/s_ri/s_free reuse next iteration
    }

    // --- per-box sums/counts of variance ---
    const float* vrow = g_var + (size_t)b * GG;
#pragma unroll
    for (int k = 0; k < CELLS_PER_THR; k++) {
        int f = flag[k];
        if (gidx[k] >= 0 && f >= 0) {
            atomicAdd(&s_sums[f], vrow[gidx[k]]);
            atomicAdd(&s_counts[f], 1);
        }
    }
    __syncthreads();
    if (t < MM) {
        int c = s_counts[t];
        if (c > 0) {
            atomicAdd(&s_loss, s_sums[t] / (float)c);
            atomicAdd(&s_pos, 1);
        }
    }
    __syncthreads();
    if (t == 0) {
        atomicAdd(&g_loss_sum, s_loss);
        atomicAdd(&g_pos, s_pos);
    }
}

__global__ void final_kernel(float* __restrict__ out) {
    int p = g_pos;
    if (p < 1) p = 1;
    out[0] = -g_loss_sum / (float)p;
}

extern "C" void kernel_launch(void* const* d_in, const int* in_sizes, int n_in,
                              void* d_out, int out_size) {
    const float* atten = (const float*)d_in[0];   // (16, 1600, 2048) fp32
    const float* bbox  = (const float*)d_in[1];   // (16, 64, 7) fp32
    float* out = (float*)d_out;

    init_kernel<<<1, 1>>>();
    var_kernel<<<BB * GG, 256>>>(atten);
    assign_kernel<<<BB, 256>>>(bbox);
    final_kernel<<<1, 1>>>(out);
}

// round 2
// speedup vs baseline: 1.8688x; 1.8688x over previous
#include <cuda_runtime.h>
#include <math.h>

#define BB 16
#define GG 1600
#define DD 2048
#define MM 64
#define WG 40
#define NCHUNK 7   // ceil(1600/256)

// ---- device-global scratch (no allocations allowed) ----
__device__ float g_var[BB * GG];
__device__ unsigned long long g_mask[BB * GG];
__device__ float g_loss_sum;
__device__ int   g_pos;
__device__ int   g_done;

// One CTA per (b,g) row: variance over D=2048 with ddof=1.
// Shift by 0.5 before accumulating (inputs are U[0,1]) to kill the
// cancellation in sumsq - sum^2/n. Block 0 also resets the accumulators.
__global__ void __launch_bounds__(256) var_kernel(const float* __restrict__ atten) {
    const int row = blockIdx.x;
    const int t = threadIdx.x;
    if (row == 0 && t == 0) {
        g_loss_sum = 0.0f;
        g_pos = 0;
        g_done = 0;
    }
    const float4* p = reinterpret_cast<const float4*>(atten + (size_t)row * DD);

    float s = 0.0f, s2 = 0.0f;
#pragma unroll
    for (int k = 0; k < 2; k++) {
        float4 v = p[t + k * 256];
        float a0 = v.x - 0.5f, a1 = v.y - 0.5f, a2 = v.z - 0.5f, a3 = v.w - 0.5f;
        s += a0; s += a1; s += a2; s += a3;
        s2 = fmaf(a0, a0, s2);
        s2 = fmaf(a1, a1, s2);
        s2 = fmaf(a2, a2, s2);
        s2 = fmaf(a3, a3, s2);
    }
#pragma unroll
    for (int o = 16; o > 0; o >>= 1) {
        s  += __shfl_xor_sync(0xFFFFFFFFu, s,  o);
        s2 += __shfl_xor_sync(0xFFFFFFFFu, s2, o);
    }
    __shared__ float sh[8], sh2[8];
    if ((t & 31) == 0) { sh[t >> 5] = s; sh2[t >> 5] = s2; }
    __syncthreads();
    if (t == 0) {
        float S = 0.0f, S2 = 0.0f;
#pragma unroll
        for (int i = 0; i < 8; i++) { S += sh[i]; S2 += sh2[i]; }
        g_var[row] = (S2 - S * S / (float)DD) / (float)(DD - 1);
    }
}

// Per-cell 64-bit inside-mask over all boxes of the batch.
// grid = (7, 16): blockIdx.y = batch, blockIdx.x = 256-cell chunk.
__global__ void __launch_bounds__(256) mask_kernel(const float* __restrict__ bboxes) {
    const int b = blockIdx.y;
    const int t = threadIdx.x;
    const int cell = blockIdx.x * 256 + t;

    __shared__ float s_corx[MM][4], s_cory[MM][4];
    if (t < MM) {
        const float* bbp = bboxes + ((size_t)b * MM + t) * 7;
        float cx = bbp[0], cy = bbp[1];
        float l = bbp[3], w = bbp[4];
        float ang = bbp[6];
        float rl = fminf(fmaxf(2.56f / l, 1.0f), 6.0f);
        float rw = fminf(fmaxf(2.56f / w, 1.0f), 6.0f);
        float el = l * rl, ew = w * rw;
        float c = cosf(ang), sn = sinf(ang);
        const float cnx[4] = {-0.5f, -0.5f, 0.5f, 0.5f};
        const float cny[4] = {-0.5f,  0.5f, 0.5f, -0.5f};
#pragma unroll
        for (int k = 0; k < 4; k++) {
            float lx = cnx[k] * el, ly = cny[k] * ew;
            s_corx[t][k] = c * lx - sn * ly + cx;
            s_cory[t][k] = sn * lx + c * ly + cy;
        }
    }
    __syncthreads();
    if (cell >= GG) return;

    const int wi = cell % WG, hi = cell / WG;
    const float px = ((float)wi + 0.5f) / 40.0f * 102.4f - 51.2f;
    const float py = ((float)hi + 0.5f) / 40.0f * 102.4f - 51.2f;

    unsigned long long m = 0ull;
    for (int i = 0; i < MM; i++) {
        const float x0 = s_corx[i][0], y0 = s_cory[i][0];
        const float x1 = s_corx[i][1], y1 = s_cory[i][1];
        const float x2 = s_corx[i][2], y2 = s_cory[i][2];
        const float x3 = s_corx[i][3], y3 = s_cory[i][3];
        const float e0x = x1 - x0, e0y = y1 - y0;
        const float e1x = x2 - x1, e1y = y2 - y1;
        const float e2x = x3 - x2, e2y = y3 - y2;
        const float e3x = x0 - x3, e3y = y0 - y3;
        float c0 = e0x * (py - y0) - e0y * (px - x0);
        float c1 = e1x * (py - y1) - e1y * (px - x1);
        float c2 = e2x * (py - y2) - e2y * (px - x2);
        float c3 = e3x * (py - y3) - e3y * (px - x3);
        bool allpos = (c0 >= 0.0f) & (c1 >= 0.0f) & (c2 >= 0.0f) & (c3 >= 0.0f);
        bool allneg = (c0 <= 0.0f) & (c1 <= 0.0f) & (c2 <= 0.0f) & (c3 <= 0.0f);
        if (allpos | allneg) m |= (1ull << i);
    }
    g_mask[(size_t)b * GG + cell] = m;
}

// One CTA per batch: warp-per-box argmin, 1-barrier-per-box sequential scan
// over precomputed masks, per-box means, global accumulation + last-CTA finalize.
__global__ void __launch_bounds__(256) assign_kernel(const float* __restrict__ bboxes,
                                                     float* __restrict__ out) {
    const int b = blockIdx.x;
    const int t = threadIdx.x;
    const int w = t >> 5, l = t & 31;

    __shared__ float s_px[GG], s_py[GG];
    __shared__ float s_cx[MM], s_cy[MM];
    __shared__ int   s_gmin[MM];
    __shared__ float s_sums[MM];
    __shared__ int   s_counts[MM];
    __shared__ float s_loss;
    __shared__ int   s_pos;

    if (t < MM) {
        const float* bbp = bboxes + ((size_t)b * MM + t) * 7;
        s_cx[t] = bbp[0];
        s_cy[t] = bbp[1];
        s_sums[t] = 0.0f;
        s_counts[t] = 0;
    }
    if (t == 0) { s_loss = 0.0f; s_pos = 0; }
    for (int c = t; c < GG; c += 256) {
        int wi = c % WG, hi = c / WG;
        s_px[c] = ((float)wi + 0.5f) / 40.0f * 102.4f - 51.2f;
        s_py[c] = ((float)hi + 0.5f) / 40.0f * 102.4f - 51.2f;
    }

    // load per-cell masks into registers (cells t, t+256, ..., t+1536)
    unsigned long long msk[NCHUNK];
    int flag[NCHUNK];
#pragma unroll
    for (int k = 0; k < NCHUNK; k++) {
        int c = t + k * 256;
        msk[k] = (c < GG) ? g_mask[(size_t)b * GG + c] : 0ull;
        flag[k] = -1;
    }
    __syncthreads();

    // warp-per-box argmin of squared distance (unique cell indices ->
    // lexicographic (d, idx) min == jnp.argmin first-occurrence)
#pragma unroll 1
    for (int j = 0; j < 8; j++) {
        const int box = w * 8 + j;
        const float cx = s_cx[box], cy = s_cy[box];
        float bd = 3.0e38f;
        int   bi = GG;
        for (int c = l; c < GG; c += 32) {
            float dx = s_px[c] - cx, dy = s_py[c] - cy;
            float d = dx * dx + dy * dy;
            if (d < bd) { bd = d; bi = c; }
        }
#pragma unroll
        for (int off = 16; off > 0; off >>= 1) {
            float od = __shfl_xor_sync(0xFFFFFFFFu, bd, off);
            int   oi = __shfl_xor_sync(0xFFFFFFFFu, bi, off);
            if (od < bd || (od == bd && oi < bi)) { bd = od; bi = oi; }
        }
        if (l == 0) s_gmin[box] = bi;
    }
    __syncthreads();

    // OR the argmin cell into the owning thread's mask
    for (int i = 0; i < MM; i++) {
        int gm = s_gmin[i];
        if ((gm & 255) == t) msk[gm >> 8] |= (1ull << i);
    }

    // sequential scan over boxes: exactly 1 barrier per box
    for (int i = 0; i < MM; i++) {
        const unsigned long long bit = 1ull << i;
        bool conflict = false;
#pragma unroll
        for (int k = 0; k < NCHUNK; k++)
            if ((msk[k] & bit) && flag[k] != -1) conflict = true;
        const int all_free = __syncthreads_and((int)(!conflict));
#pragma unroll
        for (int k = 0; k < NCHUNK; k++)
            if (msk[k] & bit) flag[k] = (all_free || flag[k] == -1) ? i : -1;
    }

    // per-box sums/counts of variance
    const float* vrow = g_var + (size_t)b * GG;
#pragma unroll
    for (int k = 0; k < NCHUNK; k++) {
        int c = t + k * 256;
        int f = flag[k];
        if (c < GG && f >= 0) {
            atomicAdd(&s_sums[f], vrow[c]);
            atomicAdd(&s_counts[f], 1);
        }
    }
    __syncthreads();
    if (t < MM) {
        int cnt = s_counts[t];
        if (cnt > 0) {
            atomicAdd(&s_loss, s_sums[t] / (float)cnt);
            atomicAdd(&s_pos, 1);
        }
    }
    __syncthreads();
    if (t == 0) {
        atomicAdd(&g_loss_sum, s_loss);
        atomicAdd(&g_pos, s_pos);
        __threadfence();
        int d = atomicAdd(&g_done, 1);
        if (d == BB - 1) {
            __threadfence();
            float ls = *(volatile float*)&g_loss_sum;
            int   p  = *(volatile int*)&g_pos;
            if (p < 1) p = 1;
            out[0] = -ls / (float)p;
        }
    }
}

extern "C" void kernel_launch(void* const* d_in, const int* in_sizes, int n_in,
                              void* d_out, int out_size) {
    const float* atten = (const float*)d_in[0];   // (16, 1600, 2048) fp32
    const float* bbox  = (const float*)d_in[1];   // (16, 64, 7) fp32
    float* out = (float*)d_out;

    var_kernel<<<BB * GG, 256>>>(atten);
    mask_kernel<<<dim3(NCHUNK, BB), 256>>>(bbox);
    assign_kernel<<<BB, 256>>>(bbox, out);
}

// round 3
// speedup vs baseline: 2.4188x; 1.2943x over previous
#include <cuda_runtime.h>
#include <math.h>

#define BB 16
#define GG 1600
#define DD 2048
#define MM 64
#define WG 40
#define NCHUNK 7   // ceil(1600/256)

// ---- device-global scratch (no allocations allowed) ----
__device__ float g_var[BB * GG];
__device__ unsigned long long g_mask[BB * GG];
__device__ float g_loss_sum;
__device__ int   g_pos;
__device__ int   g_done;

// Warp-per-row variance (MLP=16, no block barrier for the var path) fused
// with the per-cell inside-mask computation on the first 112 blocks.
// grid = 3200 blocks x 256 threads; row = blockIdx*8 + warp.
__global__ void __launch_bounds__(256) var_mask_kernel(const float* __restrict__ atten,
                                                       const float* __restrict__ bboxes) {
    const int t = threadIdx.x;
    if (blockIdx.x == 0 && t == 0) { g_loss_sum = 0.0f; g_pos = 0; g_done = 0; }

    // ---- variance: one warp per (b,g) row ----
    const int row  = blockIdx.x * 8 + (t >> 5);
    const int lane = t & 31;
    const float4* p = reinterpret_cast<const float4*>(atten) + (size_t)row * (DD / 4);

    // shift by 0.5 (inputs U[0,1]) to kill cancellation in sumsq - sum^2/n;
    // two accumulator pairs to halve the serial FADD/FFMA chains.
    float sa = 0.0f, sb = 0.0f, qa = 0.0f, qb = 0.0f;
#pragma unroll
    for (int j = 0; j < 16; j++) {
        float4 v = __ldcs(p + lane + 32 * j);
        float a0 = v.x - 0.5f, a1 = v.y - 0.5f, a2 = v.z - 0.5f, a3 = v.w - 0.5f;
        sa += a0; sb += a1; sa += a2; sb += a3;
        qa = fmaf(a0, a0, qa); qb = fmaf(a1, a1, qb);
        qa = fmaf(a2, a2, qa); qb = fmaf(a3, a3, qb);
    }
    float s = sa + sb, s2 = qa + qb;
#pragma unroll
    for (int o = 16; o > 0; o >>= 1) {
        s  += __shfl_xor_sync(0xFFFFFFFFu, s,  o);
        s2 += __shfl_xor_sync(0xFFFFFFFFu, s2, o);
    }
    if (lane == 0)
        g_var[row] = (s2 - s * s / (float)DD) / (float)(DD - 1);

    // ---- fused mask: blocks 0..111 each handle one (batch, 256-cell chunk) ----
    if (blockIdx.x < NCHUNK * BB) {
        const int b     = blockIdx.x / NCHUNK;
        const int chunk = blockIdx.x % NCHUNK;

        __shared__ float s_corx[MM][4], s_cory[MM][4];
        if (t < MM) {
            const float* bbp = bboxes + ((size_t)b * MM + t) * 7;
            float cx = bbp[0], cy = bbp[1];
            float l = bbp[3], w = bbp[4];
            float ang = bbp[6];
            float rl = fminf(fmaxf(2.56f / l, 1.0f), 6.0f);
            float rw = fminf(fmaxf(2.56f / w, 1.0f), 6.0f);
            float el = l * rl, ew = w * rw;
            float c = cosf(ang), sn = sinf(ang);
            const float cnx[4] = {-0.5f, -0.5f, 0.5f, 0.5f};
            const float cny[4] = {-0.5f,  0.5f, 0.5f, -0.5f};
#pragma unroll
            for (int k = 0; k < 4; k++) {
                float lx = cnx[k] * el, ly = cny[k] * ew;
                s_corx[t][k] = c * lx - sn * ly + cx;
                s_cory[t][k] = sn * lx + c * ly + cy;
            }
        }
        __syncthreads();

        const int cell = chunk * 256 + t;
        if (cell < GG) {
            const int wi = cell % WG, hi = cell / WG;
            const float px = ((float)wi + 0.5f) / 40.0f * 102.4f - 51.2f;
            const float py = ((float)hi + 0.5f) / 40.0f * 102.4f - 51.2f;

            unsigned long long m = 0ull;
            for (int i = 0; i < MM; i++) {
                const float x0 = s_corx[i][0], y0 = s_cory[i][0];
                const float x1 = s_corx[i][1], y1 = s_cory[i][1];
                const float x2 = s_corx[i][2], y2 = s_cory[i][2];
                const float x3 = s_corx[i][3], y3 = s_cory[i][3];
                const float e0x = x1 - x0, e0y = y1 - y0;
                const float e1x = x2 - x1, e1y = y2 - y1;
                const float e2x = x3 - x2, e2y = y3 - y2;
                const float e3x = x0 - x3, e3y = y0 - y3;
                float c0 = e0x * (py - y0) - e0y * (px - x0);
                float c1 = e1x * (py - y1) - e1y * (px - x1);
                float c2 = e2x * (py - y2) - e2y * (px - x2);
                float c3 = e3x * (py - y3) - e3y * (px - x3);
                bool allpos = (c0 >= 0.0f) & (c1 >= 0.0f) & (c2 >= 0.0f) & (c3 >= 0.0f);
                bool allneg = (c0 <= 0.0f) & (c1 <= 0.0f) & (c2 <= 0.0f) & (c3 <= 0.0f);
                if (allpos | allneg) m |= (1ull << i);
            }
            g_mask[(size_t)b * GG + cell] = m;
        }
    }
}

// One CTA per batch. Analytic 4x4-window argmin (contains all fp-rounded tie
// candidates of the global argmin; lexicographic (d, idx) min == jnp.argmin
// first-occurrence, d computed with reference-exact rn mul/add), then the
// 64-box sequential scan at 1 barrier/box, per-box means, global accumulation,
// last-CTA finalize.
__global__ void __launch_bounds__(256) assign_kernel(const float* __restrict__ bboxes,
                                                     float* __restrict__ out) {
    const int b = blockIdx.x;
    const int t = threadIdx.x;

    __shared__ int   s_gmin[MM];
    __shared__ float s_sums[MM];
    __shared__ int   s_counts[MM];
    __shared__ float s_loss;
    __shared__ int   s_pos;

    if (t < MM) {
        const float* bbp = bboxes + ((size_t)b * MM + t) * 7;
        const float cx = bbp[0], cy = bbp[1];
        s_sums[t] = 0.0f;
        s_counts[t] = 0;

        float wf = (cx + 51.2f) / 2.56f - 0.5f;
        float hf = (cy + 51.2f) / 2.56f - 0.5f;
        int w0 = (int)floorf(wf) - 1;
        int h0 = (int)floorf(hf) - 1;
        w0 = min(max(w0, 0), WG - 4);
        h0 = min(max(h0, 0), WG - 4);

        float bd = 3.0e38f;
        int   bg = 1 << 30;
#pragma unroll
        for (int dh = 0; dh < 4; dh++) {
#pragma unroll
            for (int dw = 0; dw < 4; dw++) {
                int hi = h0 + dh, wi = w0 + dw;
                float px = ((float)wi + 0.5f) / 40.0f * 102.4f - 51.2f;
                float py = ((float)hi + 0.5f) / 40.0f * 102.4f - 51.2f;
                float dx = __fsub_rn(px, cx), dy = __fsub_rn(py, cy);
                float d = __fadd_rn(__fmul_rn(dx, dx), __fmul_rn(dy, dy));
                // iteration order is ascending linear index -> strict < keeps
                // the first occurrence, matching jnp.argmin
                if (d < bd) { bd = d; bg = hi * WG + wi; }
            }
        }
        s_gmin[t] = bg;
    }
    if (t == 0) { s_loss = 0.0f; s_pos = 0; }

    // per-thread cell masks/flags in registers (cells t, t+256, ..., t+1536)
    unsigned long long msk[NCHUNK];
    int flag[NCHUNK];
#pragma unroll
    for (int k = 0; k < NCHUNK; k++) {
        int c = t + k * 256;
        msk[k] = (c < GG) ? g_mask[(size_t)b * GG + c] : 0ull;
        flag[k] = -1;
    }
    __syncthreads();

    // OR each box's argmin cell into the owning thread's mask
    for (int i = 0; i < MM; i++) {
        int gm = s_gmin[i];
        if ((gm & 255) == t) msk[gm >> 8] |= (1ull << i);
    }

    // sequential scan over boxes: exactly 1 barrier per box
    for (int i = 0; i < MM; i++) {
        const unsigned long long bit = 1ull << i;
        bool conflict = false;
#pragma unroll
        for (int k = 0; k < NCHUNK; k++)
            if ((msk[k] & bit) && flag[k] != -1) conflict = true;
        const int all_free = __syncthreads_and((int)(!conflict));
#pragma unroll
        for (int k = 0; k < NCHUNK; k++)
            if (msk[k] & bit) flag[k] = (all_free || flag[k] == -1) ? i : -1;
    }

    // per-box sums/counts of variance
    const float* vrow = g_var + (size_t)b * GG;
#pragma unroll
    for (int k = 0; k < NCHUNK; k++) {
        int c = t + k * 256;
        int f = flag[k];
        if (c < GG && f >= 0) {
            atomicAdd(&s_sums[f], vrow[c]);
            atomicAdd(&s_counts[f], 1);
        }
    }
    __syncthreads();
    if (t < MM) {
        int cnt = s_counts[t];
        if (cnt > 0) {
            atomicAdd(&s_loss, s_sums[t] / (float)cnt);
            atomicAdd(&s_pos, 1);
        }
    }
    __syncthreads();
    if (t == 0) {
        atomicAdd(&g_loss_sum, s_loss);
        atomicAdd(&g_pos, s_pos);
        __threadfence();
        int d = atomicAdd(&g_done, 1);
        if (d == BB - 1) {
            __threadfence();
            float ls = *(volatile float*)&g_loss_sum;
            int   p  = *(volatile int*)&g_pos;
            if (p < 1) p = 1;
            out[0] = -ls / (float)p;
        }
    }
}

extern "C" void kernel_launch(void* const* d_in, const int* in_sizes, int n_in,
                              void* d_out, int out_size) {
    const float* atten = (const float*)d_in[0];   // (16, 1600, 2048) fp32
    const float* bbox  = (const float*)d_in[1];   // (16, 64, 7) fp32
    float* out = (float*)d_out;

    var_mask_kernel<<<BB * GG / 8, 256>>>(atten, bbox);
    assign_kernel<<<BB, 256>>>(bbox, out);
}

// round 4
// speedup vs baseline: 2.5095x; 1.0375x over previous
#include <cuda_runtime.h>
#include <math.h>

#define BB 16
#define GG 1600
#define DD 2048
#define MM 64
#define WG 40
#define NBLK_VAR (BB * GG / 8)   // 3200 blocks, warp-per-row

// ---- device-global scratch (no allocations allowed) ----
__device__ int   g_flag[BB * GG];
__device__ float g_sums[BB * MM];
__device__ int   g_cnt[BB * MM];
__device__ int   g_done;

// One thread per cell. flag(cell) = parity(mask)? msb(mask) : -1, where mask =
// inside-bits | argmin-bits. (The reference scan's all_free coupling is dead:
// a masked assigned cell always makes all_free false, so each covering box
// simply toggles the cell: -1 -> i, assigned -> -1.)
// grid = 112: blockIdx/7 = batch, blockIdx%7 = 256-cell chunk.
__global__ void __launch_bounds__(256) flags_kernel(const float* __restrict__ bboxes) {
    const int t = threadIdx.x;
    const int gid = blockIdx.x * 256 + t;
    if (gid < BB * MM) g_sums[gid] = 0.0f;
    else if (gid < 2 * BB * MM) g_cnt[gid - BB * MM] = 0;
    else if (gid == 2 * BB * MM) g_done = 0;

    const int b = blockIdx.x / 7;
    const int chunk = blockIdx.x % 7;

    __shared__ float s_corx[MM][4], s_cory[MM][4];
    __shared__ int   s_gmin[MM];

    if (t < MM) {
        const float* bbp = bboxes + ((size_t)b * MM + t) * 7;
        float cx = bbp[0], cy = bbp[1];
        float l = bbp[3], w = bbp[4];
        float ang = bbp[6];
        float rl = fminf(fmaxf(2.56f / l, 1.0f), 6.0f);
        float rw = fminf(fmaxf(2.56f / w, 1.0f), 6.0f);
        float el = l * rl, ew = w * rw;
        float c = cosf(ang), sn = sinf(ang);
        const float cnx[4] = {-0.5f, -0.5f, 0.5f, 0.5f};
        const float cny[4] = {-0.5f,  0.5f, 0.5f, -0.5f};
#pragma unroll
        for (int k = 0; k < 4; k++) {
            float lx = cnx[k] * el, ly = cny[k] * ew;
            s_corx[t][k] = c * lx - sn * ly + cx;
            s_cory[t][k] = sn * lx + c * ly + cy;
        }

        // analytic argmin: 4x4 clamped window around the center contains all
        // fp-rounded tie candidates; lexicographic (d, idx) min with
        // reference-exact rn arithmetic == jnp.argmin first-occurrence.
        float wf = (cx + 51.2f) / 2.56f - 0.5f;
        float hf = (cy + 51.2f) / 2.56f - 0.5f;
        int w0 = min(max((int)floorf(wf) - 1, 0), WG - 4);
        int h0 = min(max((int)floorf(hf) - 1, 0), WG - 4);
        float bd = 3.0e38f;
        int   bg = 1 << 30;
#pragma unroll
        for (int dh = 0; dh < 4; dh++) {
#pragma unroll
            for (int dw = 0; dw < 4; dw++) {
                int hi = h0 + dh, wi = w0 + dw;
                float px = ((float)wi + 0.5f) / 40.0f * 102.4f - 51.2f;
                float py = ((float)hi + 0.5f) / 40.0f * 102.4f - 51.2f;
                float dx = __fsub_rn(px, cx), dy = __fsub_rn(py, cy);
                float d = __fadd_rn(__fmul_rn(dx, dx), __fmul_rn(dy, dy));
                if (d < bd) { bd = d; bg = hi * WG + wi; }
            }
        }
        s_gmin[t] = bg;
    }
    __syncthreads();

    const int cell = chunk * 256 + t;
    if (cell >= GG) return;

    const int wi = cell % WG, hi = cell / WG;
    const float px = ((float)wi + 0.5f) / 40.0f * 102.4f - 51.2f;
    const float py = ((float)hi + 0.5f) / 40.0f * 102.4f - 51.2f;

    unsigned long long m = 0ull;
#pragma unroll 4
    for (int i = 0; i < MM; i++) {
        const float x0 = s_corx[i][0], y0 = s_cory[i][0];
        const float x1 = s_corx[i][1], y1 = s_cory[i][1];
        const float x2 = s_corx[i][2], y2 = s_cory[i][2];
        const float x3 = s_corx[i][3], y3 = s_cory[i][3];
        const float e0x = x1 - x0, e0y = y1 - y0;
        const float e1x = x2 - x1, e1y = y2 - y1;
        const float e2x = x3 - x2, e2y = y3 - y2;
        const float e3x = x0 - x3, e3y = y0 - y3;
        float c0 = e0x * (py - y0) - e0y * (px - x0);
        float c1 = e1x * (py - y1) - e1y * (px - x1);
        float c2 = e2x * (py - y2) - e2y * (px - x2);
        float c3 = e3x * (py - y3) - e3y * (px - x3);
        bool allpos = (c0 >= 0.0f) & (c1 >= 0.0f) & (c2 >= 0.0f) & (c3 >= 0.0f);
        bool allneg = (c0 <= 0.0f) & (c1 <= 0.0f) & (c2 <= 0.0f) & (c3 <= 0.0f);
        bool ins = (allpos | allneg) | (s_gmin[i] == cell);
        if (ins) m |= (1ull << i);
    }
    g_flag[b * GG + cell] = (__popcll(m) & 1) ? (63 - __clzll(m)) : -1;
}

// Warp-per-row variance (MLP=16) + direct gather into per-(batch,box)
// accumulators; last CTA finalizes the loss.
__global__ void __launch_bounds__(256) var_gather_kernel(const float* __restrict__ atten,
                                                         float* __restrict__ out) {
    const int t = threadIdx.x;
    const int row  = blockIdx.x * 8 + (t >> 5);
    const int lane = t & 31;
    const float4* p = reinterpret_cast<const float4*>(atten) + (size_t)row * (DD / 4);

    // shift by 0.5 (inputs U[0,1]) to kill cancellation in sumsq - sum^2/n
    float sa = 0.0f, sb = 0.0f, qa = 0.0f, qb = 0.0f;
#pragma unroll
    for (int j = 0; j < 16; j++) {
        float4 v = __ldcs(p + lane + 32 * j);
        float a0 = v.x - 0.5f, a1 = v.y - 0.5f, a2 = v.z - 0.5f, a3 = v.w - 0.5f;
        sa += a0; sb += a1; sa += a2; sb += a3;
        qa = fmaf(a0, a0, qa); qb = fmaf(a1, a1, qb);
        qa = fmaf(a2, a2, qa); qb = fmaf(a3, a3, qb);
    }
    float s = sa + sb, s2 = qa + qb;
#pragma unroll
    for (int o = 16; o > 0; o >>= 1) {
        s  += __shfl_xor_sync(0xFFFFFFFFu, s,  o);
        s2 += __shfl_xor_sync(0xFFFFFFFFu, s2, o);
    }

    if (lane == 0) {
        float var = (s2 - s * s / (float)DD) / (float)(DD - 1);
        int f = g_flag[row];
        if (f >= 0) {
            int b = row / GG;
            atomicAdd(&g_sums[b * MM + f], var);
            atomicAdd(&g_cnt[b * MM + f], 1);
        }
    }

    // last-CTA finalize
    __threadfence();
    __syncthreads();
    __shared__ int s_tk;
    if (t == 0) s_tk = atomicAdd(&g_done, 1);
    __syncthreads();
    if (s_tk == NBLK_VAR - 1 && t < 32) {
        __threadfence();
        float loss = 0.0f;
        int   pos  = 0;
        for (int j = t; j < BB * MM; j += 32) {
            int   c  = __ldcg(&g_cnt[j]);
            float sm = __ldcg(&g_sums[j]);
            if (c > 0) { loss += sm / (float)c; pos++; }
        }
#pragma unroll
        for (int o = 16; o > 0; o >>= 1) {
            loss += __shfl_xor_sync(0xFFFFFFFFu, loss, o);
            pos  += __shfl_xor_sync(0xFFFFFFFFu, pos,  o);
        }
        if (t == 0) {
            if (pos < 1) pos = 1;
            out[0] = -loss / (float)pos;
        }
    }
}

extern "C" void kernel_launch(void* const* d_in, const int* in_sizes, int n_in,
                              void* d_out, int out_size) {
    const float* atten = (const float*)d_in[0];   // (16, 1600, 2048) fp32
    const float* bbox  = (const float*)d_in[1];   // (16, 64, 7) fp32
    float* out = (float*)d_out;

    flags_kernel<<<7 * BB, 256>>>(bbox);
    var_gather_kernel<<<NBLK_VAR, 256>>>(atten, out);
}